// round 9
// baseline (speedup 1.0000x reference)
#include <cuda_runtime.h>
#include <cuda_bf16.h>
#include <cstdint>

// PerspectiveNet768x2, int16, 2 positions per CTA.
//
// Cross-round model: L2 ceiling ~23.4 TB/s (implied consistently by R2/R3/R8);
// int16 kernels reach only 75-77% L2 vs R2's 85.5% because short CTAs spend
// ~20% of their life in prologue/epilogue bubbles. R9 halves the bubble
// fraction (2 positions/CTA, one staging sync, fused epilogue) and doubles
// per-thread MLP by interleaving the two positions' independent row loads.
// Numerics identical to R3/R4/R8 (rel_err 2.560972e-4).

#define NACT        32
#define THREADS     256
#define NFEAT       3840
#define WPR         512u            // uint32 words per 1024-col row
#define ZROW        (2u * NFEAT)    // all-zero row (device arrays zero-init)
#define QSCALE      40940.0f        // 2047 / 0.05
#define QINV        (1.0f / 40940.0f)

// [white 0..3839 | black 3840..7679 | zero row 7680]
__device__ __align__(256) unsigned g_q[(2u * NFEAT + 1u) * WPR];

__global__ void convert_kernel(const float2* __restrict__ Ww,
                               const float2* __restrict__ Wb)
{
    const unsigned n = NFEAT * WPR;
    unsigned i = blockIdx.x * blockDim.x + threadIdx.x;
    if (i >= n) return;
    float2 a = __ldg(&Ww[i]);
    int q0 = __float2int_rn(a.x * QSCALE);
    int q1 = __float2int_rn(a.y * QSCALE);
    g_q[i] = ((unsigned)q0 & 0xFFFFu) | ((unsigned)q1 << 16);
    float2 c = __ldg(&Wb[i]);
    int p0 = __float2int_rn(c.x * QSCALE);
    int p1 = __float2int_rn(c.y * QSCALE);
    g_q[n + i] = ((unsigned)p0 & 0xFFFFu) | ((unsigned)p1 << 16);
}

__device__ __forceinline__ int lo16(unsigned w) { return (int)((short)(w & 0xFFFFu)); }
__device__ __forceinline__ int hi16(unsigned w) { return (int)((short)(w >> 16)); }

__device__ __forceinline__ void vacc(uint4& a, const uint4 v) {
    a.x = __vadd2(a.x, v.x);  a.y = __vadd2(a.y, v.y);
    a.z = __vadd2(a.z, v.z);  a.w = __vadd2(a.w, v.w);
}

__global__ __launch_bounds__(THREADS)
void nnue_gather_kernel(
    const int*    __restrict__ fw,    // [B,32]
    const int*    __restrict__ fb,    // [B,32]
    const int*    __restrict__ stm,   // [B] int32
    const float4* __restrict__ bw,    // [256]  (1024 floats)
    const float4* __restrict__ bb,
    const float4* __restrict__ Wout,  // [512]  (2048 floats)
    const float*  __restrict__ bout,
    float*        __restrict__ out)   // [B]
{
    __shared__ unsigned sidx[2][2 * NACT];   // [pos][white 0..31 | black 32..63]
    __shared__ float    sred[2][THREADS / 32];

    const int cta = blockIdx.x;
    const int tid = threadIdx.x;
    const int b0  = cta * 2;             // first of this CTA's two positions

    // Stage 128 row ids in one pass (threads 0..127).
    if (tid < 128) {
        const int pos = tid >> 6;        // 0 or 1
        const int k   = tid & 63;
        unsigned r;
        if (k < NACT) {
            int v = fw[(b0 + pos) * NACT + k];
            r = (v < 0) ? ZROW : (unsigned)v;
        } else {
            int v = fb[(b0 + pos) * NACT + (k - NACT)];
            r = (v < 0) ? ZROW : (unsigned)v + NFEAT;
        }
        sidx[pos][k] = r;
    }
    __syncthreads();

    const int persp = tid >> 7;          // 0 = white, 1 = black
    const int t     = tid & 127;         // 8-col group within the perspective
    const unsigned* base = g_q + (unsigned)t * 4u;
    const unsigned* i0 = sidx[0] + persp * NACT;
    const unsigned* i1 = sidx[1] + persp * NACT;

    // Per position: two 16-feature SIMD partials (max 16*2047 < 32767).
    uint4 aA = make_uint4(0u,0u,0u,0u), aB = make_uint4(0u,0u,0u,0u);  // pos0
    uint4 cA = make_uint4(0u,0u,0u,0u), cB = make_uint4(0u,0u,0u,0u);  // pos1

    // Interleave the two positions' rows: 8 independent LDG.128 in flight.
    #pragma unroll
    for (int i = 0; i < 16; i += 4) {
        const uint4 v0 = *(const uint4*)(base + (size_t)i0[i + 0] * WPR);
        const uint4 v1 = *(const uint4*)(base + (size_t)i0[i + 1] * WPR);
        const uint4 v2 = *(const uint4*)(base + (size_t)i0[i + 2] * WPR);
        const uint4 v3 = *(const uint4*)(base + (size_t)i0[i + 3] * WPR);
        const uint4 w0 = *(const uint4*)(base + (size_t)i1[i + 0] * WPR);
        const uint4 w1 = *(const uint4*)(base + (size_t)i1[i + 1] * WPR);
        const uint4 w2 = *(const uint4*)(base + (size_t)i1[i + 2] * WPR);
        const uint4 w3 = *(const uint4*)(base + (size_t)i1[i + 3] * WPR);
        vacc(aA, v0); vacc(aA, v1); vacc(aA, v2); vacc(aA, v3);
        vacc(cA, w0); vacc(cA, w1); vacc(cA, w2); vacc(cA, w3);
    }
    #pragma unroll
    for (int i = 16; i < 32; i += 4) {
        const uint4 v0 = *(const uint4*)(base + (size_t)i0[i + 0] * WPR);
        const uint4 v1 = *(const uint4*)(base + (size_t)i0[i + 1] * WPR);
        const uint4 v2 = *(const uint4*)(base + (size_t)i0[i + 2] * WPR);
        const uint4 v3 = *(const uint4*)(base + (size_t)i0[i + 3] * WPR);
        const uint4 w0 = *(const uint4*)(base + (size_t)i1[i + 0] * WPR);
        const uint4 w1 = *(const uint4*)(base + (size_t)i1[i + 1] * WPR);
        const uint4 w2 = *(const uint4*)(base + (size_t)i1[i + 2] * WPR);
        const uint4 w3 = *(const uint4*)(base + (size_t)i1[i + 3] * WPR);
        vacc(aB, v0); vacc(aB, v1); vacc(aB, v2); vacc(aB, v3);
        vacc(cB, w0); vacc(cB, w1); vacc(cB, w2); vacc(cB, w3);
    }

    // Epilogue for both positions.
    const float4* bias = (persp == 0) ? bw : bb;
    const float4 bv0 = bias[t * 2];
    const float4 bv1 = bias[t * 2 + 1];

    const bool wh0 = (__ldg(&stm[b0])     != 0);
    const bool wh1 = (__ldg(&stm[b0 + 1]) != 0);
    const int  h0  = ((persp == 0) == wh0) ? 0 : 256;
    const int  h1  = ((persp == 0) == wh1) ? 0 : 256;
    const float4 u0 = Wout[h0 + t * 2], u1 = Wout[h0 + t * 2 + 1];
    const float4 q0 = Wout[h1 + t * 2], q1 = Wout[h1 + t * 2 + 1];

    #define COL(wA, wB, EXT, bvc, wc)                                   \
        ({ int   _c = EXT(wA) + EXT(wB);                                \
           float _h = fmaf((float)_c, QINV, (bvc));                     \
           _h = fminf(fmaxf(_h, 0.0f), 1.0f);                           \
           _h * _h * (wc); })

    float p0 = 0.0f, p1 = 0.0f;
    p0 += COL(aA.x, aB.x, lo16, bv0.x, u0.x);
    p0 += COL(aA.x, aB.x, hi16, bv0.y, u0.y);
    p0 += COL(aA.y, aB.y, lo16, bv0.z, u0.z);
    p0 += COL(aA.y, aB.y, hi16, bv0.w, u0.w);
    p0 += COL(aA.z, aB.z, lo16, bv1.x, u1.x);
    p0 += COL(aA.z, aB.z, hi16, bv1.y, u1.y);
    p0 += COL(aA.w, aB.w, lo16, bv1.z, u1.z);
    p0 += COL(aA.w, aB.w, hi16, bv1.w, u1.w);

    p1 += COL(cA.x, cB.x, lo16, bv0.x, q0.x);
    p1 += COL(cA.x, cB.x, hi16, bv0.y, q0.y);
    p1 += COL(cA.y, cB.y, lo16, bv0.z, q0.z);
    p1 += COL(cA.y, cB.y, hi16, bv0.w, q0.w);
    p1 += COL(cA.z, cB.z, lo16, bv1.x, q1.x);
    p1 += COL(cA.z, cB.z, hi16, bv1.y, q1.y);
    p1 += COL(cA.w, cB.w, lo16, bv1.z, q1.z);
    p1 += COL(cA.w, cB.w, hi16, bv1.w, q1.w);
    #undef COL

    // Reduce both positions with one sync.
    #pragma unroll
    for (int o = 16; o > 0; o >>= 1) {
        p0 += __shfl_down_sync(0xffffffffu, p0, o);
        p1 += __shfl_down_sync(0xffffffffu, p1, o);
    }
    if ((tid & 31) == 0) {
        sred[0][tid >> 5] = p0;
        sred[1][tid >> 5] = p1;
    }
    __syncthreads();

    if (tid < 2) {
        float s = 0.0f;
        #pragma unroll
        for (int k = 0; k < THREADS / 32; ++k) s += sred[tid][k];
        out[b0 + tid] = s + bout[0];
    }
}

extern "C" void kernel_launch(void* const* d_in, const int* in_sizes, int n_in,
                              void* d_out, int out_size)
{
    const int*    fw   = (const int*)d_in[0];
    const int*    fb   = (const int*)d_in[1];
    const int*    stm  = (const int*)d_in[2];
    const float2* Ww   = (const float2*)d_in[3];
    const float4* bw   = (const float4*)d_in[4];
    const float2* Wb   = (const float2*)d_in[5];
    const float4* bb   = (const float4*)d_in[6];
    const float4* Wout = (const float4*)d_in[7];
    const float*  bout = (const float*)d_in[8];
    float*        out  = (float*)d_out;

    const int B = in_sizes[0] / NACT;   // 16384

    const unsigned nwords = NFEAT * WPR;
    convert_kernel<<<(nwords + 255) / 256, 256>>>(Ww, Wb);
    nnue_gather_kernel<<<B / 2, THREADS>>>(fw, fb, stm, bw, bb, Wout, bout, out);
}